// round 2
// baseline (speedup 1.0000x reference)
#include <cuda_runtime.h>
#include <cuda_bf16.h>

// NASPolicy: 20-step LSTM(128) controller, batch 1, 6-way softmax heads.
// Strategy:
//   Phase A (20 blocks in parallel): xw[t][row] = x_t @ W_ih[row] + b_ih + b_hh
//   Phase B (blocks 0..3 persistent): sequential 20-step recurrence with
//     W_hh register-resident (128 floats/thread, 128 rows/CTA = 4 gates x 32 cells).
//     Cross-CTA h exchange through global mem + atomic phase barrier.
//   Phase C: softmax heads for all 20 steps computed in parallel (5 steps/block).

#define CELL   128
#define STEPS  20
#define NOUT   6
#define NREC   4      // recurrence blocks
#define NPRE   20     // prologue blocks (== grid size)

__device__ float        g_xw[STEPS * 4 * CELL];   // precomputed input-path gates
__device__ float        g_h [STEPS * CELL];       // h history
__device__ unsigned int g_ctr[32];                // phase barrier counters

__device__ __forceinline__ unsigned int ld_acq_u32(const unsigned int* p) {
    unsigned int v;
    asm volatile("ld.acquire.gpu.u32 %0, [%1];" : "=r"(v) : "l"(p) : "memory");
    return v;
}
__device__ __forceinline__ float ld_acq_f32(const float* p) {
    float v;
    asm volatile("ld.acquire.gpu.f32 %0, [%1];" : "=f"(v) : "l"(p) : "memory");
    return v;
}
__device__ __forceinline__ float sigf(float x) { return 1.0f / (1.0f + expf(-x)); }

__global__ void reset_ctr_kernel() {
    if (threadIdx.x < 32) g_ctr[threadIdx.x] = 0u;
}

__global__ void __launch_bounds__(128, 1)
nas_policy_kernel(const int*   __restrict__ net,
                  const float* __restrict__ emb_start,
                  const float* __restrict__ emb_keys,   // [4,6,128]
                  const float* __restrict__ fcW,        // [4,6,128]
                  const float* __restrict__ fcb,        // [4,6]
                  const float* __restrict__ Wih,        // [512,128]
                  const float* __restrict__ Whh,        // [512,128]
                  const float* __restrict__ bih,        // [512]
                  const float* __restrict__ bhh,        // [512]
                  float*       __restrict__ out)        // [20,1,6]
{
    __shared__ float sh_x[CELL];
    __shared__ float h_s[CELL];
    __shared__ float g_s[4 * 32];
    __shared__ float sm_log[5][NOUT];

    const int t = threadIdx.x;
    const int b = blockIdx.x;

    // ---------------- Phase A: xw for step = b ----------------
    // x_b: emb_start for step 0, else emb_keys[(b-1)%4, net[b-1]]
    if (b == 0) {
        sh_x[t] = emb_start[t];
    } else {
        int ps = b - 1;
        sh_x[t] = emb_keys[(ps & 3) * (NOUT * CELL) + net[ps] * CELL + t];
    }
    __syncthreads();

    #pragma unroll
    for (int gg = 0; gg < 4; gg++) {
        int r = gg * CELL + t;
        const float4* wr = reinterpret_cast<const float4*>(Wih + r * CELL);
        const float4* xr = reinterpret_cast<const float4*>(sh_x);
        float a0 = 0.f, a1 = 0.f, a2 = 0.f, a3 = 0.f;
        #pragma unroll
        for (int i = 0; i < 32; i++) {
            float4 w4 = wr[i];
            float4 x4 = xr[i];
            a0 += w4.x * x4.x; a1 += w4.y * x4.y;
            a2 += w4.z * x4.z; a3 += w4.w * x4.w;
        }
        g_xw[b * (4 * CELL) + r] = (a0 + a1) + (a2 + a3) + bih[r] + bhh[r];
    }
    __threadfence();     // each thread fences its own xw stores
    __syncthreads();
    if (t == 0) atomicAdd(&g_ctr[0], 1u);
    if (b >= NREC) return;   // prologue-only blocks exit after arrival

    // ---------------- Phase B: persistent recurrence (blocks 0..3) ----------------
    const int gate = t >> 5;           // 0..3 (i,f,g,o)
    const int j    = t & 31;           // cell within this CTA's chunk
    const int grow = gate * CELL + b * 32 + j;   // global gate row

    // W_hh row register-resident (overlaps with waiting for phase-A barrier)
    float w[CELL];
    {
        const float4* whr = reinterpret_cast<const float4*>(Whh + grow * CELL);
        #pragma unroll
        for (int i = 0; i < 32; i++) {
            float4 v = whr[i];
            w[4*i+0] = v.x; w[4*i+1] = v.y; w[4*i+2] = v.z; w[4*i+3] = v.w;
        }
    }

    if (t == 0) { while (ld_acq_u32(&g_ctr[0]) < NPRE) { } }
    __syncthreads();

    h_s[t] = 0.0f;
    float c = 0.0f;   // cell state, owned by threads t<32 (cell j = t)
    __syncthreads();

    for (int step = 0; step < STEPS; step++) {
        // input-path gate value (fresh address each step; issued early, used last)
        float xwv = g_xw[step * (4 * CELL) + grow];

        float a0 = 0.f, a1 = 0.f, a2 = 0.f, a3 = 0.f;
        const float4* hr = reinterpret_cast<const float4*>(h_s);
        #pragma unroll
        for (int i = 0; i < 32; i++) {
            float4 h4 = hr[i];   // broadcast, conflict-free
            a0 += w[4*i+0] * h4.x; a1 += w[4*i+1] * h4.y;
            a2 += w[4*i+2] * h4.z; a3 += w[4*i+3] * h4.w;
        }
        g_s[t] = (a0 + a1) + (a2 + a3) + xwv;
        __syncthreads();

        if (t < 32) {
            float iv = sigf(g_s[t]);
            float fv = sigf(g_s[32 + t]);
            float gv = tanhf(g_s[64 + t]);
            float ov = sigf(g_s[96 + t]);
            c = fv * c + iv * gv;
            float h = ov * tanhf(c);
            g_h[step * CELL + b * 32 + t] = h;
            __threadfence();
        }
        __syncthreads();

        if (t == 0) {
            atomicAdd(&g_ctr[1 + step], 1u);
            while (ld_acq_u32(&g_ctr[1 + step]) < NREC) { }
        }
        __syncthreads();

        // stage full h for next step
        h_s[t] = ld_acq_f32(&g_h[step * CELL + t]);
        __syncthreads();
    }

    // ---------------- Phase C: softmax heads, 5 steps per block ----------------
    if (t < 5 * NOUT) {
        int sl = t / NOUT;          // 0..4
        int o  = t % NOUT;
        int s  = b * 5 + sl;
        const float4* hv = reinterpret_cast<const float4*>(g_h + s * CELL);
        const float4* fv = reinterpret_cast<const float4*>(fcW + ((s & 3) * NOUT + o) * CELL);
        float a0 = 0.f, a1 = 0.f, a2 = 0.f, a3 = 0.f;
        #pragma unroll
        for (int i = 0; i < 32; i++) {
            float4 h4 = hv[i];
            float4 w4 = fv[i];
            a0 += h4.x * w4.x; a1 += h4.y * w4.y;
            a2 += h4.z * w4.z; a3 += h4.w * w4.w;
        }
        sm_log[sl][o] = (a0 + a1) + (a2 + a3) + fcb[(s & 3) * NOUT + o];
    }
    __syncthreads();
    if (t < 5) {
        int s = b * 5 + t;
        float m = sm_log[t][0];
        #pragma unroll
        for (int o = 1; o < NOUT; o++) m = fmaxf(m, sm_log[t][o]);
        float e[NOUT];
        float sum = 0.f;
        #pragma unroll
        for (int o = 0; o < NOUT; o++) { e[o] = expf(sm_log[t][o] - m); sum += e[o]; }
        float inv = 1.0f / sum;
        #pragma unroll
        for (int o = 0; o < NOUT; o++) out[s * NOUT + o] = e[o] * inv;
    }
}

extern "C" void kernel_launch(void* const* d_in, const int* in_sizes, int n_in,
                              void* d_out, int out_size) {
    const int*   net       = (const int*)  d_in[0];
    // d_in[1] = reward (unused)
    const float* emb_start = (const float*)d_in[2];
    const float* emb_keys  = (const float*)d_in[3];
    const float* fcW       = (const float*)d_in[4];
    const float* fcb       = (const float*)d_in[5];
    const float* Wih       = (const float*)d_in[6];
    const float* Whh       = (const float*)d_in[7];
    const float* bih       = (const float*)d_in[8];
    const float* bhh       = (const float*)d_in[9];
    float* out = (float*)d_out;

    reset_ctr_kernel<<<1, 32>>>();   // counters must be zero on every graph replay
    nas_policy_kernel<<<NPRE, 128>>>(net, emb_start, emb_keys, fcW, fcb,
                                     Wih, Whh, bih, bhh, out);
}

// round 4
// speedup vs baseline: 1.4264x; 1.4264x over previous
#include <cuda_runtime.h>
#include <cuda_bf16.h>
#include <cstdint>

// NASPolicy: 20-step LSTM(128) controller, batch 1, 6-way softmax heads.
// R3: 4-CTA CGA recurrence with DSMEM h-exchange + cluster barrier
//     (replaces global-atomic barrier + __threadfence + ld.acquire spins).
//
// Phase A (20 blocks): xw[t][row] = x_t @ W_ih[row] + b_ih + b_hh  (parallel over steps)
// Phase B (cluster of blocks 0..3): sequential 20-step recurrence; W_hh register-
//   resident (128 f32/thread); h broadcast to all 4 CTAs' smem via st.shared::cluster;
//   per-step sync = barrier.cluster (release/acquire covers DSMEM stores).
// Phase C: softmax heads from smem-resident h history, 5 steps per CTA.

#define CELL   128
#define STEPS  20
#define NOUT   6
#define NREC   4
#define NPRE   20

__device__ float        g_xw[STEPS * 4 * CELL];   // precomputed input-path gates
__device__ unsigned int g_ctr[32];                // phase-A arrival counter

__device__ __forceinline__ unsigned int ld_acq_u32(const unsigned int* p) {
    unsigned int v;
    asm volatile("ld.acquire.gpu.u32 %0, [%1];" : "=r"(v) : "l"(p) : "memory");
    return v;
}
__device__ __forceinline__ uint32_t smem_u32(const void* p) {
    uint32_t a;
    asm("{ .reg .u64 t; cvta.to.shared.u64 t, %1; cvt.u32.u64 %0, t; }"
        : "=r"(a) : "l"(p));
    return a;
}
__device__ __forceinline__ uint32_t mapa_rank(uint32_t addr, uint32_t rank) {
    uint32_t r;
    asm("mapa.shared::cluster.u32 %0, %1, %2;" : "=r"(r) : "r"(addr), "r"(rank));
    return r;
}
__device__ __forceinline__ void st_cluster_f32(uint32_t addr, float v) {
    asm volatile("st.shared::cluster.f32 [%0], %1;" :: "r"(addr), "f"(v) : "memory");
}
__device__ __forceinline__ void cluster_sync() {
    asm volatile("barrier.cluster.arrive.aligned;" ::: "memory");
    asm volatile("barrier.cluster.wait.aligned;"   ::: "memory");
}
__device__ __forceinline__ float sigf(float x) { return 1.0f / (1.0f + expf(-x)); }

__global__ void reset_ctr_kernel() {
    if (threadIdx.x < 32) g_ctr[threadIdx.x] = 0u;
}

__global__ void __launch_bounds__(128, 1) __cluster_dims__(NREC, 1, 1)
nas_policy_kernel(const int*   __restrict__ net,
                  const float* __restrict__ emb_start,
                  const float* __restrict__ emb_keys,   // [4,6,128]
                  const float* __restrict__ fcW,        // [4,6,128]
                  const float* __restrict__ fcb,        // [4,6]
                  const float* __restrict__ Wih,        // [512,128]
                  const float* __restrict__ Whh,        // [512,128]
                  const float* __restrict__ bih,        // [512]
                  const float* __restrict__ bhh,        // [512]
                  float*       __restrict__ out)        // [20,1,6]
{
    __shared__ __align__(16) float h_hist[(STEPS + 1) * CELL]; // h_hist[0]=h0, [s+1]=h after step s
    __shared__ float sh_x[CELL];
    __shared__ float act[4 * 32];
    __shared__ float sm_log[5][NOUT];

    const int t = threadIdx.x;
    const int b = blockIdx.x;

    // ---------------- Phase A: xw for step = b ----------------
    if (b == 0) {
        sh_x[t] = emb_start[t];
    } else {
        int ps = b - 1;
        sh_x[t] = emb_keys[(ps & 3) * (NOUT * CELL) + net[ps] * CELL + t];
    }
    __syncthreads();

    #pragma unroll
    for (int gg = 0; gg < 4; gg++) {
        int r = gg * CELL + t;
        const float4* wr = reinterpret_cast<const float4*>(Wih + r * CELL);
        const float4* xr = reinterpret_cast<const float4*>(sh_x);
        float a0 = 0.f, a1 = 0.f, a2 = 0.f, a3 = 0.f;
        #pragma unroll
        for (int i = 0; i < 32; i++) {
            float4 w4 = wr[i];
            float4 x4 = xr[i];
            a0 += w4.x * x4.x; a1 += w4.y * x4.y;
            a2 += w4.z * x4.z; a3 += w4.w * x4.w;
        }
        g_xw[b * (4 * CELL) + r] = (a0 + a1) + (a2 + a3) + bih[r] + bhh[r];
    }
    __threadfence();
    __syncthreads();
    if (t == 0) atomicAdd(&g_ctr[0], 1u);
    if (b >= NREC) return;   // non-recurrence clusters exit after phase A

    // ---------------- Phase B: cluster recurrence (blocks 0..3) ----------------
    uint32_t rank;
    asm("mov.u32 %0, %%cluster_ctarank;" : "=r"(rank));

    const int gate = t >> 5;                      // 0..3 (i,f,g,o)
    const int j    = t & 31;                      // cell within this CTA's chunk
    const int grow = gate * CELL + (int)rank * 32 + j;

    // W_hh row register-resident (load overlaps the phase-A wait)
    float w[CELL];
    {
        const float4* whr = reinterpret_cast<const float4*>(Whh + grow * CELL);
        #pragma unroll
        for (int i = 0; i < 32; i++) {
            float4 v = whr[i];
            w[4*i+0] = v.x; w[4*i+1] = v.y; w[4*i+2] = v.z; w[4*i+3] = v.w;
        }
    }

    h_hist[t] = 0.0f;        // h0 = 0 (local region; peers only write h_hist[1..])
    if (t == 0) { while (ld_acq_u32(&g_ctr[0]) < NPRE) { } }
    __syncthreads();

    float c = 0.0f;          // cell state owned by threads t<32 (cell = rank*32 + t)

    for (int step = 0; step < STEPS; step++) {
        float xwv = g_xw[step * (4 * CELL) + grow];   // L2 load, hidden under FMAs

        const float4* hr = reinterpret_cast<const float4*>(h_hist + step * CELL);
        float a0 = 0.f, a1 = 0.f, a2 = 0.f, a3 = 0.f;
        #pragma unroll
        for (int i = 0; i < 32; i++) {
            float4 h4 = hr[i];   // broadcast, conflict-free
            a0 += w[4*i+0] * h4.x; a1 += w[4*i+1] * h4.y;
            a2 += w[4*i+2] * h4.z; a3 += w[4*i+3] * h4.w;
        }
        float gv = (a0 + a1) + (a2 + a3) + xwv;
        act[t] = (gate == 2) ? tanhf(gv) : sigf(gv);   // activate own gate in parallel
        __syncthreads();

        if (t < 32) {
            float iv = act[t], fv = act[32 + t], ggv = act[64 + t], ov = act[96 + t];
            c = fv * c + iv * ggv;
            float h = ov * tanhf(c);
            // broadcast h into every cluster CTA's h_hist (incl. self)
            uint32_t la = smem_u32(&h_hist[(step + 1) * CELL + rank * 32 + t]);
            #pragma unroll
            for (uint32_t r = 0; r < NREC; r++)
                st_cluster_f32(mapa_rank(la, r), h);
        }
        cluster_sync();   // release our DSMEM stores, acquire peers'
    }

    // ---------------- Phase C: softmax heads, 5 steps per CTA (smem h) ----------------
    if (t < 5 * NOUT) {
        int sl = t / NOUT;
        int o  = t % NOUT;
        int s  = (int)rank * 5 + sl;
        const float4* hv = reinterpret_cast<const float4*>(h_hist + (s + 1) * CELL);
        const float4* fv = reinterpret_cast<const float4*>(fcW + ((s & 3) * NOUT + o) * CELL);
        float a0 = 0.f, a1 = 0.f, a2 = 0.f, a3 = 0.f;
        #pragma unroll
        for (int i = 0; i < 32; i++) {
            float4 h4 = hv[i];
            float4 w4 = fv[i];
            a0 += h4.x * w4.x; a1 += h4.y * w4.y;
            a2 += h4.z * w4.z; a3 += h4.w * w4.w;
        }
        sm_log[sl][o] = (a0 + a1) + (a2 + a3) + fcb[(s & 3) * NOUT + o];
    }
    __syncthreads();
    if (t < 5) {
        int s = (int)rank * 5 + t;
        float m = sm_log[t][0];
        #pragma unroll
        for (int o = 1; o < NOUT; o++) m = fmaxf(m, sm_log[t][o]);
        float e[NOUT];
        float sum = 0.f;
        #pragma unroll
        for (int o = 0; o < NOUT; o++) { e[o] = expf(sm_log[t][o] - m); sum += e[o]; }
        float inv = 1.0f / sum;
        #pragma unroll
        for (int o = 0; o < NOUT; o++) out[s * NOUT + o] = e[o] * inv;
    }
}

extern "C" void kernel_launch(void* const* d_in, const int* in_sizes, int n_in,
                              void* d_out, int out_size) {
    const int*   net       = (const int*)  d_in[0];
    // d_in[1] = reward (unused)
    const float* emb_start = (const float*)d_in[2];
    const float* emb_keys  = (const float*)d_in[3];
    const float* fcW       = (const float*)d_in[4];
    const float* fcb       = (const float*)d_in[5];
    const float* Wih       = (const float*)d_in[6];
    const float* Whh       = (const float*)d_in[7];
    const float* bih       = (const float*)d_in[8];
    const float* bhh       = (const float*)d_in[9];
    float* out = (float*)d_out;

    reset_ctr_kernel<<<1, 32>>>();
    nas_policy_kernel<<<NPRE, 128>>>(net, emb_start, emb_keys, fcW, fcb,
                                     Wih, Whh, bih, bhh, out);
}